// round 10
// baseline (speedup 1.0000x reference)
#include <cuda_runtime.h>
#include <math.h>

#define C_DT    0.01f
#define C_STEPS 100
#define C_NCHNK 5
#define C_CHUNK 20
#define C_NOSC  50
#define C_NPER  50
#define C_LIM   1.0471975511965976f   /* pi/3 */
#define C_MGL2  4.905f                /* m*g*(l/2), I = 1 */
#define NBP     13                    /* producer blocks: 4 oscillators each (52, 2 padded) */

/* [step][128]: slots bid*8 + q*2 + quad (104 used); 104..127 stay 0 forever */
__device__ __align__(128) float g_tq[C_STEPS * 128];
__device__ unsigned g_chunk[C_NCHNK];                 /* consumer resets each run */

__global__ __launch_bounds__(128, 1)
void cpg_fused(const float* __restrict__ x,
               const float* __restrict__ fc1_w, const float* __restrict__ fc1_b,
               const float* __restrict__ fc2_w, const float* __restrict__ fc2_b,
               const float* __restrict__ fc3_w, const float* __restrict__ fc3_b,
               const float* __restrict__ fcd_w, const float* __restrict__ fcd_b,
               const float* __restrict__ fc4_w, const float* __restrict__ fc4_b,
               const float* __restrict__ enc,  const float* __restrict__ osc_bias,
               const float* __restrict__ dec,
               float* __restrict__ out)
{
    const int tid = threadIdx.x;
    const int bid = blockIdx.x;
    const float x0 = x[0], x1 = x[1];

    if (bid < NBP) {
        // ============================ PRODUCER ============================
        __shared__ float sh_h[128];
        __shared__ float sh_h2[128];
        __shared__ float sh_o[8];

        // warp0: per-neuron constants. 8 lanes/osc, 4 osc/warp, 7 neurons/lane.
        float e0[7], e1[7], bb[7], d0[7], d1[7], w4[7];
        if (tid < 32) {
            const int q   = tid >> 3;
            const int l8  = tid & 7;
            const int osc = bid * 4 + q;
            #pragma unroll
            for (int k = 0; k < 7; ++k) {
                int n = l8 + 8 * k;
                if (osc < C_NOSC && n < C_NPER) {
                    int idx = osc * C_NPER + n;
                    e0[k] = enc[idx * 2 + 0];
                    e1[k] = enc[idx * 2 + 1];
                    bb[k] = osc_bias[idx];
                    d0[k] = dec[osc * 2 * C_NPER + n];
                    d1[k] = dec[osc * 2 * C_NPER + C_NPER + n];
                    w4[k] = fc4_w[idx];
                } else {
                    e0[k] = e1[k] = bb[k] = d0[k] = d1[k] = w4[k] = 0.f;
                }
            }
        }

        // prefetch first 8 fc2 float4s before the barrier (hide L2 latency)
        const float4* wr2 = (const float4*)(fc2_w + tid * 128);
        float4 p0 = wr2[0], p1 = wr2[1], p2 = wr2[2], p3 = wr2[3];
        float4 p4 = wr2[4], p5 = wr2[5], p6 = wr2[6], p7 = wr2[7];

        // h = relu(fc1 x + b1)
        {
            float v = fmaf(fc1_w[tid * 2], x0, fmaf(fc1_w[tid * 2 + 1], x1, fc1_b[tid]));
            sh_h[tid] = fmaxf(v, 0.f);
        }
        __syncthreads();

        // h2 = relu(fc2 h + b2)
        {
            float a0 = 0.f, a1 = 0.f, a2 = 0.f, a3 = 0.f;
            const float4 pre[8] = {p0, p1, p2, p3, p4, p5, p6, p7};
            #pragma unroll
            for (int j = 0; j < 8; ++j) {
                float4 w = pre[j];
                a0 = fmaf(w.x, sh_h[4 * j + 0], a0);
                a1 = fmaf(w.y, sh_h[4 * j + 1], a1);
                a2 = fmaf(w.z, sh_h[4 * j + 2], a2);
                a3 = fmaf(w.w, sh_h[4 * j + 3], a3);
            }
            #pragma unroll 8
            for (int j = 8; j < 32; ++j) {
                float4 w = wr2[j];
                a0 = fmaf(w.x, sh_h[4 * j + 0], a0);
                a1 = fmaf(w.y, sh_h[4 * j + 1], a1);
                a2 = fmaf(w.z, sh_h[4 * j + 2], a2);
                a3 = fmaf(w.w, sh_h[4 * j + 3], a3);
            }
            sh_h2[tid] = fmaxf((a0 + a1) + (a2 + a3) + fc2_b[tid], 0.f);
        }
        __syncthreads();

        // warp1: this block's 8 fc3 rows -> o0 (guard row < 100)
        if (tid >= 32 && tid < 64) {
            const int r     = (tid - 32) >> 2;
            const int lane4 = tid & 3;
            const int row   = bid * 8 + r;
            float s = 0.f;
            if (row < 2 * C_NOSC) {
                const float* wr = fc3_w + row * 128 + lane4 * 32;
                const float* hv = sh_h2 + lane4 * 32;
                #pragma unroll 8
                for (int k = 0; k < 32; ++k) s = fmaf(wr[k], hv[k], s);
            }
            s += __shfl_down_sync(0xffffffffu, s, 2, 4);
            s += __shfl_down_sync(0xffffffffu, s, 1, 4);
            if (lane4 == 0) sh_o[r] = (row < 2 * C_NOSC) ? s + fc3_b[row] : 0.f;
        }
        __syncthreads();

        // warp0: recurrence with deferred 3rd butterfly level.
        if (tid < 32) {
            const int q  = tid >> 3;
            const int l8 = tid & 7;
            float de0[7], de1[7];
            #pragma unroll
            for (int k = 0; k < 7; ++k) { de0[k] = C_DT * e0[k]; de1[k] = C_DT * e1[k]; }

            float u0  = sh_o[2 * q];       // u(t-1) carried; init = o0 (B=0)
            float u1  = sh_o[2 * q + 1];
            float B0v = 0.f, B1v = 0.f;    // cross-quad sums, carried
            float* slot = g_tq + bid * 8 + q * 2 + (l8 >> 2);

            for (int c = 0; c < C_NCHNK; ++c) {
                for (int i = 0; i < C_CHUNK; ++i) {
                    const int s = c * C_CHUNK + i;

                    // full state s(t) from carried u,B — off the encode path
                    float s0full = fmaf(C_DT, B0v, u0);
                    float s1full = fmaf(C_DT, B1v, u1);

                    // encode: P from u (ready), fold B (late) last
                    float a0a = 0.f, a1a = 0.f, ata = 0.f;
                    float a0b = 0.f, a1b = 0.f, atb = 0.f;
                    #pragma unroll
                    for (int k = 0; k < 4; ++k) {
                        float P = fmaf(e0[k], u0, fmaf(e1[k], u1, bb[k]));
                        float z = fmaf(de0[k], B0v, fmaf(de1[k], B1v, P));
                        float a = fmaxf(z, 0.f);
                        a0a = fmaf(d0[k], a, a0a);
                        a1a = fmaf(d1[k], a, a1a);
                        ata = fmaf(w4[k], a, ata);
                    }
                    #pragma unroll
                    for (int k = 4; k < 7; ++k) {
                        float P = fmaf(e0[k], u0, fmaf(e1[k], u1, bb[k]));
                        float z = fmaf(de0[k], B0v, fmaf(de1[k], B1v, P));
                        float a = fmaxf(z, 0.f);
                        a0b = fmaf(d0[k], a, a0b);
                        a1b = fmaf(d1[k], a, a1b);
                        atb = fmaf(w4[k], a, atb);
                    }
                    float a0 = a0a + a0b, a1 = a1a + a1b, at = ata + atb;

                    // 2-level butterfly -> quad sums
                    a0 += __shfl_xor_sync(0xffffffffu, a0, 1, 8);
                    a1 += __shfl_xor_sync(0xffffffffu, a1, 1, 8);
                    at += __shfl_xor_sync(0xffffffffu, at, 1, 8);
                    a0 += __shfl_xor_sync(0xffffffffu, a0, 2, 8);
                    a1 += __shfl_xor_sync(0xffffffffu, a1, 2, 8);
                    at += __shfl_xor_sync(0xffffffffu, at, 2, 8);

                    // cross-quad exchange (latency hidden behind next encode's P)
                    float nB0 = __shfl_xor_sync(0xffffffffu, a0, 4, 8);
                    float nB1 = __shfl_xor_sync(0xffffffffu, a1, 4, 8);

                    u0 = fmaf(C_DT, a0, s0full);
                    u1 = fmaf(C_DT, a1, s1full);
                    B0v = nB0;
                    B1v = nB1;

                    // torque quad partial (lanes 0 and 4 of each group)
                    if ((l8 & 3) == 0) slot[s * 128] = at;
                }
                // publish chunk c: fence all lanes' stores, sync, one atomic
                __threadfence();
                __syncwarp();
                if (tid == 0) atomicAdd(&g_chunk[c], 1u);
            }
        }
    } else {
        // ============================ CONSUMER ============================
        __shared__ float sh_h[128];
        __shared__ float sh_direct;
        __shared__ float sh_torque[C_STEPS];
        __shared__ float sh_l[2 * C_STEPS];

        // h = relu(fc1 x + b1); warp0 computes direct (overlaps producers)
        {
            float v = fmaf(fc1_w[tid * 2], x0, fmaf(fc1_w[tid * 2 + 1], x1, fc1_b[tid]));
            sh_h[tid] = fmaxf(v, 0.f);
        }
        __syncthreads();
        if (tid < 32) {
            float s = 0.f;
            #pragma unroll
            for (int k = 0; k < 4; ++k)
                s = fmaf(fcd_w[tid + 32 * k], sh_h[tid + 32 * k], s);
            #pragma unroll
            for (int off = 16; off; off >>= 1)
                s += __shfl_down_sync(0xffffffffu, s, off);
            if (tid == 0) sh_direct = s + fcd_b[0] + fc4_b[0];
        }
        __syncthreads();
        const float direct = sh_direct;

        float th = x0, om = 0.f;   // tid 0's limb state across chunks

        for (int c = 0; c < C_NCHNK; ++c) {
            // single-thread, single-line, sleepy poll
            if (tid == 0) {
                unsigned v;
                const unsigned* cp = &g_chunk[c];
                do {
                    asm volatile("ld.acquire.gpu.global.u32 %0, [%1];" : "=r"(v) : "l"(cp));
                    if (v < NBP) __nanosleep(64);
                } while (v < NBP);
            }
            __syncthreads();

            // 20 threads: reduce this chunk's 104 quad-partials per step
            if (tid < C_CHUNK) {
                const int t = c * C_CHUNK + tid;
                const float4* row = (const float4*)(g_tq + t * 128);
                float acc = 0.f;
                #pragma unroll
                for (int j = 0; j < 26; ++j) {
                    float4 v = row[j];
                    acc += (v.x + v.y) + (v.z + v.w);
                }
                sh_torque[t] = acc + direct;
            }
            __syncthreads();

            // tid 0: limb integration for this chunk
            if (tid == 0) {
                #pragma unroll
                for (int i = 0; i < C_CHUNK; ++i) {
                    const int t = c * C_CHUNK + i;
                    float torque = sh_torque[t];
                    float th2 = fmaf(C_DT, om, th);
                    float om2 = fmaf(C_DT, torque - C_MGL2 * __sinf(th), om);
                    bool hit = (th2 > C_LIM) || (th2 < -C_LIM);
                    th2 = fminf(fmaxf(th2, -C_LIM), C_LIM);
                    om2 = hit ? 0.f : om2;
                    sh_l[2 * t]     = th2;
                    sh_l[2 * t + 1] = om2;
                    th = th2; om = om2;
                }
            }
        }
        __syncthreads();

        // reset chunk counters for next graph replay (all producers done)
        if (tid < C_NCHNK) g_chunk[tid] = 0;

        // race-free coalesced output: out[0..199]=l_states, out[200..299]=torques
        out[tid] = sh_l[tid];
        if (tid < 72)  out[128 + tid] = sh_l[128 + tid];
        if (tid < 100) out[200 + tid] = sh_torque[tid];
    }
}

extern "C" void kernel_launch(void* const* d_in, const int* in_sizes, int n_in,
                              void* d_out, int out_size) {
    const float* x        = (const float*)d_in[0];
    const float* fc1_w    = (const float*)d_in[1];
    const float* fc1_b    = (const float*)d_in[2];
    const float* fc2_w    = (const float*)d_in[3];
    const float* fc2_b    = (const float*)d_in[4];
    const float* fc3_w    = (const float*)d_in[5];
    const float* fc3_b    = (const float*)d_in[6];
    const float* fcd_w    = (const float*)d_in[7];
    const float* fcd_b    = (const float*)d_in[8];
    const float* fc4_w    = (const float*)d_in[9];
    const float* fc4_b    = (const float*)d_in[10];
    const float* enc      = (const float*)d_in[11];
    const float* osc_bias = (const float*)d_in[12];
    const float* dec      = (const float*)d_in[13];
    float* out = (float*)d_out;

    cpg_fused<<<NBP + 1, 128>>>(x, fc1_w, fc1_b, fc2_w, fc2_b, fc3_w, fc3_b,
                                fcd_w, fcd_b, fc4_w, fc4_b, enc, osc_bias, dec, out);
}

// round 11
// speedup vs baseline: 1.0979x; 1.0979x over previous
#include <cuda_runtime.h>
#include <math.h>

#define C_DT    0.01f
#define C_STEPS 100
#define C_HALF  50
#define C_NOSC  50
#define C_NPER  50
#define C_LIM   1.0471975511965976f   /* pi/3 */
#define C_MGL2  4.905f                /* m*g*(l/2), I = 1 */
#define NBP     13                    /* producer blocks: 4 oscillators each (52, 2 padded) */

/* [step][128]: slots bid*8 + q*2 + quad (104 used); never-written slots stay 0 */
__device__ __align__(128) float g_tq[C_STEPS * 128];
__device__ unsigned g_ph[2];          /* phase counters; consumer resets each run */

__global__ __launch_bounds__(128, 1)
void cpg_fused(const float* __restrict__ x,
               const float* __restrict__ fc1_w, const float* __restrict__ fc1_b,
               const float* __restrict__ fc2_w, const float* __restrict__ fc2_b,
               const float* __restrict__ fc3_w, const float* __restrict__ fc3_b,
               const float* __restrict__ fcd_w, const float* __restrict__ fcd_b,
               const float* __restrict__ fc4_w, const float* __restrict__ fc4_b,
               const float* __restrict__ enc,  const float* __restrict__ osc_bias,
               const float* __restrict__ dec,
               float* __restrict__ out)
{
    const int tid = threadIdx.x;
    const int bid = blockIdx.x;
    const float x0 = x[0], x1 = x[1];

    if (bid < NBP) {
        // ============================ PRODUCER ============================
        __shared__ float sh_h[128];
        __shared__ float sh_h2[128];
        __shared__ float sh_o[8];

        // warp0: per-neuron constants. 8 lanes/osc, 4 osc/warp, 7 neurons/lane.
        float e0[7], e1[7], bb[7], d0[7], d1[7], w4[7];
        if (tid < 32) {
            const int q   = tid >> 3;
            const int l8  = tid & 7;
            const int osc = bid * 4 + q;
            #pragma unroll
            for (int k = 0; k < 7; ++k) {
                int n = l8 + 8 * k;
                if (osc < C_NOSC && n < C_NPER) {
                    int idx = osc * C_NPER + n;
                    e0[k] = enc[idx * 2 + 0];
                    e1[k] = enc[idx * 2 + 1];
                    bb[k] = osc_bias[idx];
                    d0[k] = dec[osc * 2 * C_NPER + n];
                    d1[k] = dec[osc * 2 * C_NPER + C_NPER + n];
                    w4[k] = fc4_w[idx];
                } else {
                    e0[k] = e1[k] = bb[k] = d0[k] = d1[k] = w4[k] = 0.f;
                }
            }
        }

        // prefetch 16 fc2 float4s above the first barrier (independent of h)
        const float4* wr2 = (const float4*)(fc2_w + tid * 128);
        float4 pre[16];
        #pragma unroll
        for (int j = 0; j < 16; ++j) pre[j] = wr2[j];

        // h = relu(fc1 x + b1)
        {
            float v = fmaf(fc1_w[tid * 2], x0, fmaf(fc1_w[tid * 2 + 1], x1, fc1_b[tid]));
            sh_h[tid] = fmaxf(v, 0.f);
        }
        __syncthreads();

        // h2 = relu(fc2 h + b2)
        {
            float a0 = 0.f, a1 = 0.f, a2 = 0.f, a3 = 0.f;
            #pragma unroll
            for (int j = 0; j < 16; ++j) {
                float4 w = pre[j];
                a0 = fmaf(w.x, sh_h[4 * j + 0], a0);
                a1 = fmaf(w.y, sh_h[4 * j + 1], a1);
                a2 = fmaf(w.z, sh_h[4 * j + 2], a2);
                a3 = fmaf(w.w, sh_h[4 * j + 3], a3);
            }
            #pragma unroll 8
            for (int j = 16; j < 32; ++j) {
                float4 w = wr2[j];
                a0 = fmaf(w.x, sh_h[4 * j + 0], a0);
                a1 = fmaf(w.y, sh_h[4 * j + 1], a1);
                a2 = fmaf(w.z, sh_h[4 * j + 2], a2);
                a3 = fmaf(w.w, sh_h[4 * j + 3], a3);
            }
            sh_h2[tid] = fmaxf((a0 + a1) + (a2 + a3) + fc2_b[tid], 0.f);
        }
        __syncthreads();

        // warp1: this block's 8 fc3 rows -> o0 (guard row < 100)
        if (tid >= 32 && tid < 64) {
            const int r     = (tid - 32) >> 2;
            const int lane4 = tid & 3;
            const int row   = bid * 8 + r;
            float s = 0.f;
            if (row < 2 * C_NOSC) {
                const float* wr = fc3_w + row * 128 + lane4 * 32;
                const float* hv = sh_h2 + lane4 * 32;
                #pragma unroll 8
                for (int k = 0; k < 32; ++k) s = fmaf(wr[k], hv[k], s);
            }
            s += __shfl_down_sync(0xffffffffu, s, 2, 4);
            s += __shfl_down_sync(0xffffffffu, s, 1, 4);
            if (lane4 == 0) sh_o[r] = (row < 2 * C_NOSC) ? s + fc3_b[row] : 0.f;
        }
        __syncthreads();

        // warp0: 100-step recurrence (R7 core); publish at step 50 and at end.
        if (tid < 32) {
            const int q  = tid >> 3;
            const int l8 = tid & 7;
            float s0 = sh_o[2 * q];
            float s1 = sh_o[2 * q + 1];
            float* slot = g_tq + bid * 8 + q * 2 + (l8 >> 2);

            for (int s = 0; s < C_STEPS; ++s) {
                // split decode chains (k0-3 / k4-6) to shorten the FMA path
                float a0a = 0.f, a1a = 0.f, ata = 0.f;
                float a0b = 0.f, a1b = 0.f, atb = 0.f;
                #pragma unroll
                for (int k = 0; k < 4; ++k) {
                    float a = fmaxf(fmaf(e0[k], s0, fmaf(e1[k], s1, bb[k])), 0.f);
                    a0a = fmaf(d0[k], a, a0a);
                    a1a = fmaf(d1[k], a, a1a);
                    ata = fmaf(w4[k], a, ata);
                }
                #pragma unroll
                for (int k = 4; k < 7; ++k) {
                    float a = fmaxf(fmaf(e0[k], s0, fmaf(e1[k], s1, bb[k])), 0.f);
                    a0b = fmaf(d0[k], a, a0b);
                    a1b = fmaf(d1[k], a, a1b);
                    atb = fmaf(w4[k], a, atb);
                }
                float a0 = a0a + a0b, a1 = a1a + a1b, at = ata + atb;

                // a0/a1: full 3-level butterfly (recurrence-critical)
                a0 += __shfl_xor_sync(0xffffffffu, a0, 1, 8);
                a1 += __shfl_xor_sync(0xffffffffu, a1, 1, 8);
                at += __shfl_xor_sync(0xffffffffu, at, 1, 8);
                a0 += __shfl_xor_sync(0xffffffffu, a0, 2, 8);
                a1 += __shfl_xor_sync(0xffffffffu, a1, 2, 8);
                at += __shfl_xor_sync(0xffffffffu, at, 2, 8);   // at stops at quad level
                a0 += __shfl_xor_sync(0xffffffffu, a0, 4, 8);
                a1 += __shfl_xor_sync(0xffffffffu, a1, 4, 8);

                s0 = fmaf(C_DT, a0, s0);
                s1 = fmaf(C_DT, a1, s1);

                if ((l8 & 3) == 0) slot[s * 128] = at;  // two quad-partials per osc

                if (s == C_HALF - 1) {                  // publish phase 0
                    __threadfence();
                    __syncwarp();
                    if (tid == 0) atomicAdd(&g_ph[0], 1u);
                }
            }
            __threadfence();
            __syncwarp();
            if (tid == 0) atomicAdd(&g_ph[1], 1u);      // publish phase 1
        }
    } else {
        // ============================ CONSUMER ============================
        __shared__ float sh_h[128];
        __shared__ float sh_direct;
        __shared__ float sh_torque[C_STEPS];
        __shared__ float sh_l[2 * C_STEPS];

        // h = relu(fc1 x + b1); warp0 computes direct (overlaps producers)
        {
            float v = fmaf(fc1_w[tid * 2], x0, fmaf(fc1_w[tid * 2 + 1], x1, fc1_b[tid]));
            sh_h[tid] = fmaxf(v, 0.f);
        }
        __syncthreads();
        if (tid < 32) {
            float s = 0.f;
            #pragma unroll
            for (int k = 0; k < 4; ++k)
                s = fmaf(fcd_w[tid + 32 * k], sh_h[tid + 32 * k], s);
            #pragma unroll
            for (int off = 16; off; off >>= 1)
                s += __shfl_down_sync(0xffffffffu, s, off);
            if (tid == 0) sh_direct = s + fcd_b[0] + fc4_b[0];
        }
        __syncthreads();
        const float direct = sh_direct;

        float th = x0, om = 0.f;        // tid 0's limb state across phases
        float sv = __sinf(x0);          // software-pipelined sine

        #pragma unroll
        for (int p = 0; p < 2; ++p) {
            // single-thread, single-line, sleepy poll (R7-proven)
            if (tid == 0) {
                unsigned v;
                const unsigned* cp = &g_ph[p];
                do {
                    asm volatile("ld.acquire.gpu.global.u32 %0, [%1];" : "=r"(v) : "l"(cp));
                    if (v < NBP) __nanosleep(64);
                } while (v < NBP);
            }
            __syncthreads();

            // 50 threads: reduce this phase's 104 quad-partials per step
            if (tid < C_HALF) {
                const int t = p * C_HALF + tid;
                const float4* row = (const float4*)(g_tq + t * 128);
                float acc = 0.f;
                #pragma unroll
                for (int j = 0; j < 26; ++j) {
                    float4 v = row[j];
                    acc += (v.x + v.y) + (v.z + v.w);
                }
                sh_torque[t] = acc + direct;
            }
            __syncthreads();

            // tid 0: limb integration for this phase (sin pipelined one step ahead)
            if (tid == 0) {
                #pragma unroll 5
                for (int i = 0; i < C_HALF; ++i) {
                    const int t = p * C_HALF + i;
                    float torque = sh_torque[t];
                    float th2 = fmaf(C_DT, om, th);
                    float om2 = fmaf(C_DT, torque - C_MGL2 * sv, om);
                    bool hit = (th2 > C_LIM) || (th2 < -C_LIM);
                    th2 = fminf(fmaxf(th2, -C_LIM), C_LIM);
                    om2 = hit ? 0.f : om2;
                    sh_l[2 * t]     = th2;
                    sh_l[2 * t + 1] = om2;
                    th = th2; om = om2;
                    sv = __sinf(th);     // overlaps next iteration's compare/select
                }
            }
        }
        __syncthreads();

        // reset phase counters for the next graph replay (all producers done)
        if (tid < 2) g_ph[tid] = 0;

        // race-free coalesced output: out[0..199]=l_states, out[200..299]=torques
        out[tid] = sh_l[tid];
        if (tid < 72)  out[128 + tid] = sh_l[128 + tid];
        if (tid < 100) out[200 + tid] = sh_torque[tid];
    }
}

extern "C" void kernel_launch(void* const* d_in, const int* in_sizes, int n_in,
                              void* d_out, int out_size) {
    const float* x        = (const float*)d_in[0];
    const float* fc1_w    = (const float*)d_in[1];
    const float* fc1_b    = (const float*)d_in[2];
    const float* fc2_w    = (const float*)d_in[3];
    const float* fc2_b    = (const float*)d_in[4];
    const float* fc3_w    = (const float*)d_in[5];
    const float* fc3_b    = (const float*)d_in[6];
    const float* fcd_w    = (const float*)d_in[7];
    const float* fcd_b    = (const float*)d_in[8];
    const float* fc4_w    = (const float*)d_in[9];
    const float* fc4_b    = (const float*)d_in[10];
    const float* enc      = (const float*)d_in[11];
    const float* osc_bias = (const float*)d_in[12];
    const float* dec      = (const float*)d_in[13];
    float* out = (float*)d_out;

    cpg_fused<<<NBP + 1, 128>>>(x, fc1_w, fc1_b, fc2_w, fc2_b, fc3_w, fc3_b,
                                fcd_w, fcd_b, fc4_w, fc4_b, enc, osc_bias, dec, out);
}